// round 13
// baseline (speedup 1.0000x reference)
#include <cuda_runtime.h>
#include <cuda_fp16.h>

#define NPIXT 262144   // B*H*W = 4*256*256
#define HWSZ  65536    // H*W
#define NCH   32
#define NBLK  1024     // NPIXT / 256
#define TINYF 1.17549435e-38f
#define INFF  __int_as_float(0x7f800000)

// ---------------- scratch (__device__ globals: allocation-free, zero-init) -----------
__device__ __half2 g_pk[NPIXT * 32];   // per-pixel, per-channel (mw, den) fp16 pairs
__device__ int   g_tblV[8 * NPIXT];    // rank table, valid
__device__ int   g_tblH[8 * NPIXT];    // rank table, hard
__device__ unsigned g_agg [16 * NBLK]; // decoupled-lookback: block aggregate+1 (0 = pending)
__device__ unsigned g_incl[16 * NBLK]; // decoupled-lookback: inclusive prefix+1 (0 = pending)
__device__ int   g_done;               // blocks-finished counter (reset by finalize)
__device__ int   g_count[8];
__device__ int   g_hcount[8];
__device__ float g_protoAcc[768];      // [k][s][c]; zero at entry of every launch
__device__ float g_posMW[8 * NCH];     // proto_mu_n * proto_w
__device__ float g_posDen[8 * NCH];    // proto_sigma * proto_w
__device__ float g_simL[8 * 7];        // sim/TEMP logits per (i,k)
__device__ float g_vnInv;

__device__ __forceinline__ unsigned ldv(const unsigned* p) {
    return *(const volatile unsigned*)p;
}

// ---------------- threefry2x32 (JAX-compatible, partitionable mode) ----------------
__device__ __forceinline__ void tf2x32(unsigned k0, unsigned k1,
                                       unsigned x0, unsigned x1,
                                       unsigned& o0, unsigned& o1) {
    unsigned ks2 = k0 ^ k1 ^ 0x1BD11BDAu;
    x0 += k0; x1 += k1;
#define TF_R(r) { x0 += x1; x1 = __funnelshift_l(x1, x1, (r)); x1 ^= x0; }
    TF_R(13) TF_R(15) TF_R(26) TF_R(6)   x0 += k1;  x1 += ks2 + 1u;
    TF_R(17) TF_R(29) TF_R(16) TF_R(24)  x0 += ks2; x1 += k0  + 2u;
    TF_R(13) TF_R(15) TF_R(26) TF_R(6)   x0 += k0;  x1 += k1  + 3u;
    TF_R(17) TF_R(29) TF_R(16) TF_R(24)  x0 += k1;  x1 += ks2 + 4u;
    TF_R(13) TF_R(15) TF_R(26) TF_R(6)   x0 += ks2; x1 += k0  + 5u;
#undef TF_R
    o0 = x0; o1 = x1;
}

__device__ __forceinline__ unsigned rbits(unsigned k0, unsigned k1, unsigned idx) {
    unsigned a, b;
    tf2x32(k0, k1, 0u, idx, a, b);
    return a ^ b;
}
__device__ __forceinline__ float u01(unsigned bits) {
    return __uint_as_float((bits >> 9) | 0x3F800000u) - 1.0f;
}

// ============ kernel 1: classify + scan(lookback) + scatter + transpose + finalize ===
__global__ void __launch_bounds__(256) k_main(const float* __restrict__ w_in,
                                              const float* __restrict__ mu_in,
                                              const float* __restrict__ sg_in,
                                              const float* __restrict__ label,
                                              const float* __restrict__ mask,
                                              const float* __restrict__ prob,
                                              float* out) {
    __shared__ float tw[32][33], tm[32][33], ts[32][33];
    __shared__ float acc[8][768];          // [warp][k*256 + s*32 + c]
    __shared__ unsigned char codes[256];
    __shared__ int wsum[8][8][2];          // [warp][class][flag]
    __shared__ int sboff[16];              // exclusive prefix per sequence
    __shared__ int sdone;
    __shared__ float sMW[8][NCH], sDen[8][NCH];
    int t = threadIdx.x, warp = t >> 5, lane = t & 31;
    int blk = blockIdx.x;
    for (int j = t; j < 8 * 768; j += 256) ((float*)acc)[j] = 0.f;

    int blockPix = blk * 256;
    int n = blockPix + t;
    int b = n >> 16, x = n & 65535;

    // ---- classify ----
    float mk = mask[b * HWSZ + x];
    int s = 0;
#pragma unroll
    for (int k = 0; k < 8; k++) {
        float lv = label[(b * 8 + k) * HWSZ + x];
        if (lv > 0.5f) s = k;
    }
    bool valid = mk > 0.0f;
    float pv = prob[(b * 8 + s) * HWSZ + x];
    bool hard = valid && (pv < 0.97f);
    codes[t] = (unsigned char)(s | (valid ? 8 : 0) | (hard ? 16 : 0));

    // per-warp stable counts + intra-warp prefixes
    unsigned lmlt = (1u << lane) - 1u;
    int prefv = 0, prefh = 0;
#pragma unroll
    for (int k = 0; k < 8; k++) {
        unsigned mv = __ballot_sync(0xffffffffu, valid && (s == k));
        unsigned mh = __ballot_sync(0xffffffffu, hard && (s == k));
        if (s == k) { prefv = __popc(mv & lmlt); prefh = __popc(mh & lmlt); }
        if (lane == 0) { wsum[warp][k][0] = __popc(mv); wsum[warp][k][1] = __popc(mh); }
    }
    __syncthreads();   // wsum, codes, acc-zero ready

    // ---- publish block aggregates (value+1 encoding) ----
    if (t < 16) {
        int c16 = 0;
#pragma unroll
        for (int w2 = 0; w2 < 8; w2++) c16 += wsum[w2][t >> 1][t & 1];
        *(volatile unsigned*)&g_agg[t * NBLK + blk] = (unsigned)c16 + 1u;
    }

    // ---- decoupled lookback: 16 half-warps, one sequence each ----
    {
        int seq = t >> 4, w = t & 15;
        unsigned sh = (unsigned)(t & 16);
        unsigned hmask = 0xFFFFu << sh;
        const unsigned* aggp = g_agg + seq * NBLK;
        const unsigned* inclp = g_incl + seq * NBLK;
        unsigned sum = 0;
        int pos = blk - 1;
        bool fin = (blk == 0);
        while (!fin) {
            int j = pos - w;
            unsigned iv = (j >= 0) ? ldv(inclp + j) : 1u;
            unsigned av = (j >= 0) ? ldv(aggp + j) : 1u;
            unsigned balI = (__ballot_sync(hmask, iv != 0u) >> sh) & 0xFFFFu;
            unsigned balA = (__ballot_sync(hmask, av != 0u) >> sh) & 0xFFFFu;
            if (balI) {
                int w0 = __ffs(balI) - 1;
                unsigned need = (1u << w0) - 1u;
                if ((balA & need) == need) {
                    unsigned contrib = (w < w0) ? (av - 1u) : ((w == w0) ? (iv - 1u) : 0u);
                    sum += __reduce_add_sync(hmask, contrib);
                    fin = true;
                }
            } else if (balA == 0xFFFFu) {
                sum += __reduce_add_sync(hmask, av - 1u);
                pos -= 16;
            }
        }
        if (w == 0) {
            int c16 = 0;
#pragma unroll
            for (int w2 = 0; w2 < 8; w2++) c16 += wsum[w2][seq >> 1][seq & 1];
            sboff[seq] = (int)sum;
            *(volatile unsigned*)&g_incl[seq * NBLK + blk] = sum + (unsigned)c16 + 1u;
        }
    }
    __syncthreads();   // sboff ready

    // ---- scatter rank tables ----
    {
        int bofv = 0, bofh = 0;
        for (int w2 = 0; w2 < warp; w2++) { bofv += wsum[w2][s][0]; bofh += wsum[w2][s][1]; }
        if (valid) {
            int r = sboff[s * 2 + 0] + bofv + prefv;
            g_tblV[s * NPIXT + r] = n;
            if (hard) {
                int rh = sboff[s * 2 + 1] + bofh + prefh;
                g_tblH[s * NPIXT + rh] = n;
            }
        }
    }

    // ---- staged transpose + prototype sums ----
    size_t base = (size_t)b * (NCH * HWSZ) + (blockPix & 65535);
#pragma unroll 1
    for (int st = 0; st < 8; st++) {
        int pixOfs = st * 32;
        __syncthreads();
#pragma unroll
        for (int i = 0; i < 4; i++) {
            int c = warp + i * 8;
            size_t a = base + (size_t)c * HWSZ + pixOfs + lane;
            tw[lane][c] = w_in[a];
            tm[lane][c] = mu_in[a];
            ts[lane][c] = sg_in[a];
        }
        __syncthreads();
#pragma unroll
        for (int j = 0; j < 4; j++) {
            int p = warp * 4 + j;
            int pin = pixOfs + p;
            int np = blockPix + pin;
            float wv = tw[p][lane];
            float mv = tm[p][lane];
            float sv = ts[p][lane];
            float nr2 = mv * mv;
#pragma unroll
            for (int ofs = 16; ofs; ofs >>= 1) nr2 += __shfl_xor_sync(0xffffffffu, nr2, ofs);
            float inv = 1.0f / fmaxf(sqrtf(nr2), 1e-12f);
            g_pk[(size_t)np * 32 + lane] = __floats2half2_rn((mv * inv) * wv, sv * wv);
            int pc = codes[pin];
            if (pc & 8) {
                int ps = pc & 7;
                float isw = __fdividef(wv, sv);
                acc[warp][0 * 256 + ps * 32 + lane] += isw;
                acc[warp][1 * 256 + ps * 32 + lane] += isw * mv;
                acc[warp][2 * 256 + ps * 32 + lane] += __frcp_rn(wv);
            }
        }
    }
    __syncthreads();
#pragma unroll
    for (int j = 0; j < 3; j++) {
        int idx = t + j * 256;
        float sum = 0.f;
#pragma unroll
        for (int w2 = 0; w2 < 8; w2++) sum += acc[w2][idx];
        if (sum != 0.f) atomicAdd(&g_protoAcc[idx], sum);
    }

    // ---- last-done block runs finalize ----
    __threadfence();
    __syncthreads();
    if (t == 0) sdone = (atomicAdd(&g_done, 1) == NBLK - 1) ? 1 : 0;
    __syncthreads();
    if (sdone) {
        if (t < 16) {
            unsigned cv = ldv(&g_incl[t * NBLK + (NBLK - 1)]) - 1u;
            if (t & 1) g_hcount[t >> 1] = (int)cv;
            else       g_count[t >> 1]  = (int)cv;
        }
        int ss = t >> 5, c = t & 31;
        float a0 = *(volatile float*)&g_protoAcc[0 * 256 + t];
        float a1 = *(volatile float*)&g_protoAcc[1 * 256 + t];
        float a2 = *(volatile float*)&g_protoAcc[2 * 256 + t];
        g_protoAcc[0 * 256 + t] = 0.f;     // restore invariant for next replay
        g_protoAcc[1 * 256 + t] = 0.f;
        g_protoAcc[2 * 256 + t] = 0.f;
        float psig = 1.0f / a0;
        float pmu = a1 / a0;
        float pw = 1.0f / a2;
        float nr2 = pmu * pmu;
#pragma unroll
        for (int ofs = 16; ofs; ofs >>= 1) nr2 += __shfl_xor_sync(0xffffffffu, nr2, ofs);
        float inv = 1.0f / fmaxf(sqrtf(nr2), 1e-12f);
        float mun = pmu * inv;
        float mw = mun * pw, den = psig * pw;
        g_posMW[ss * NCH + c] = mw;
        g_posDen[ss * NCH + c] = den;
        sMW[ss][c] = mw;
        sDen[ss][c] = den;
        __syncthreads();
        if (t < 56) {
            int i = t / 7, k = t % 7, o = (i + 1 + k) & 7;
            float sum = 0.f;
            for (int cc = 0; cc < NCH; cc++) {
                float d = sMW[i][cc] - sMW[o][cc];
                float dn = sDen[i][cc] + sDen[o][cc];
                sum += d * d / dn + logf(dn);
            }
            g_simL[i * 7 + k] = (g_count[o] > 0) ? (-sum * (1.0f / 32.0f)) : -INFF;
        }
        if (t == 0) {
            int vn = 0;
            for (int s2 = 0; s2 < 8; s2++) vn += (g_count[s2] > 0) ? 1 : 0;
            g_vnInv = (vn > 0) ? 1.0f / (float)vn : 0.f;
            out[0] = 0.f;
            g_done = 0;                    // reset for next replay
        }
    }
}

// ---------------- MLS logits ---------------------------------------------------------
__device__ __forceinline__ float mls_logit_h(const float* __restrict__ aMW,
                                             const float* __restrict__ aDen,
                                             const __half2* __restrict__ bpk) {
    const uint4* u = (const uint4*)bpk;   // 8 uint4, each = 4 channels of (mw,den)
    float total = 0.f;
#pragma unroll
    for (int g = 0; g < 8; g++) {
        uint4 v = u[g];
        const __half2* h = (const __half2*)&v;
        float qs = 0.f, prod = 1.f;
#pragma unroll
        for (int i = 0; i < 4; i++) {
            float2 md = __half22float2(h[i]);   // x=mw, y=den
            int c = g * 4 + i;
            float den = aDen[c] + md.y;
            float d = aMW[c] - md.x;
            qs += __fdividef(d * d, den);
            prod *= den;
        }
        total += qs + __logf(prod);
    }
    return -total * (1.0f / 32.0f);  // _mls/TEMP
}

__device__ __forceinline__ float mls_logit_f(const float* __restrict__ aMW,
                                             const float* __restrict__ aDen,
                                             const float* __restrict__ bMW,
                                             const float* __restrict__ bDen) {
    float total = 0.f;
#pragma unroll
    for (int g = 0; g < 4; g++) {
        float qs = 0.f, prod = 1.f;
#pragma unroll
        for (int i = 0; i < 8; i++) {
            int c = g * 8 + i;
            float den = aDen[c] + bDen[c];
            float d = aMW[c] - bMW[c];
            qs += __fdividef(d * d, den);
            prod *= den;
        }
        total += qs + __logf(prod);
    }
    return -total * (1.0f / 32.0f);
}

// ============ kernel 2: fused sampling + logits + logsumexp + CE =====================
__global__ void __launch_bounds__(256) k_slog(float* out) {
    int i = blockIdx.x, q = blockIdx.y, t = threadIdx.x;
    int warp = t >> 5, lane = t & 31;
    __shared__ unsigned sk[4];           // k2a,k2b,k3a,k3b
    __shared__ int sap;
    __shared__ float sexp[7];            // exp(-sim/TEMP) for exponential-race argmin
    __shared__ float aMW[NCH], aDen[NCH];
    __shared__ float sred[8];

    // zero lookback arrays for next replay (16384*2 words over 2048 blocks)
    {
        int bid = blockIdx.y * 8 + blockIdx.x;
        if (t < 16) {
            int zi = bid * 16 + t;
            if (zi < 16 * NBLK) g_agg[zi] = 0u;
            else                g_incl[zi - 16 * NBLK] = 0u;
        }
    }

    if (t < 7) sexp[t] = __expf(-g_simL[i * 7 + t]);
    // parallel prologue: three warps derive the three key chains
    if (t == 0) {
        unsigned ka, kb, k1a, k1b;
        tf2x32(0u, 42u, 0u, (unsigned)i, ka, kb);   // keys[i]
        tf2x32(ka, kb, 0u, 0u, k1a, k1b);           // k1
        float u = u01(rbits(k1a, k1b, (unsigned)q));
        int hc = g_hcount[i];
        int r = (int)(u * (float)hc);
        int cl = hc - 1; if (cl < 0) cl = 0;
        if (r > cl) r = cl;
        if (r < 0) r = 0;
        int ap = (hc > 0) ? g_tblH[i * NPIXT + r] : 0;
        if (ap < 0) ap = 0;
        if (ap >= NPIXT) ap = NPIXT - 1;
        sap = ap;
    } else if (t == 32) {
        unsigned ka, kb, a, b2;
        tf2x32(0u, 42u, 0u, (unsigned)i, ka, kb);
        tf2x32(ka, kb, 0u, 1u, a, b2);              // k2
        sk[0] = a; sk[1] = b2;
    } else if (t == 64) {
        unsigned ka, kb, a, b2;
        tf2x32(0u, 42u, 0u, (unsigned)i, ka, kb);
        tf2x32(ka, kb, 0u, 2u, a, b2);              // k3
        sk[2] = a; sk[3] = b2;
    }
    __syncthreads();
    if (t < NCH) {
        float2 md = __half22float2(g_pk[(size_t)sap * 32 + t]);
        aMW[t] = md.x;
        aDen[t] = md.y;
    }
    unsigned k2a = sk[0], k2b = sk[1], k3a = sk[2], k3b = sk[3];

    // ---- negative class sampling via exponential race (argmin (-ln u)*exp(-sim)) ----
    unsigned j = (unsigned)(q * 256 + t);
    unsigned b7 = j * 7u;
    float wmin = INFF;
    int bi = 0;
#pragma unroll
    for (int k = 0; k < 7; k++) {
        float u = u01(rbits(k2a, k2b, b7 + k));
        u = fmaxf(u + TINYF, TINYF);
        float wv = -__logf(u) * sexp[k];
        if (wv < wmin) { wmin = wv; bi = k; }
    }
    int cls = (i + 1 + bi) & 7;
    int cnt = g_count[cls];
    float u3 = u01(rbits(k3a, k3b, j));
    int r = (int)(u3 * (float)cnt);
    int cl = cnt - 1; if (cl < 0) cl = 0;
    if (r > cl) r = cl;
    if (r < 0) r = 0;
    int p = g_tblV[cls * NPIXT + r];
    if (p < 0) p = 0;
    if (p >= NPIXT) p = NPIXT - 1;
    __syncthreads();   // anchor smem ready

    // ---- logits: lg0 = this thread's NEGATIVE, lg1 (t==0 only) = POSITIVE ----
    float lg0 = mls_logit_h(aMW, aDen, g_pk + (size_t)p * 32);
    float lg1 = (t == 0) ? mls_logit_f(aMW, aDen, g_posMW + i * NCH, g_posDen + i * NCH)
                         : 0.f;

    // ---- logsumexp with fixed shift M=0 (logits bounded above ~4) ----
    float ex = __expf(lg0) + ((t == 0) ? __expf(lg1) : 0.f);
#pragma unroll
    for (int ofs = 16; ofs; ofs >>= 1) ex += __shfl_xor_sync(0xffffffffu, ex, ofs);
    if (lane == 0) sred[warp] = ex;
    __syncthreads();
    if (t == 0) {
        float sum = 0.f;
#pragma unroll
        for (int w2 = 0; w2 < 8; w2++) sum += sred[w2];
        float lse = __logf(sum);
        bool ok = (g_hcount[i] > 0) && (g_count[i] > 0);
        if (ok) atomicAdd(out, (lse - lg1) * g_vnInv * (1.0f / 256.0f));
    }
}

// ---------------- launch ----------------
extern "C" void kernel_launch(void* const* d_in, const int* in_sizes, int n_in,
                              void* d_out, int out_size) {
    const float* weights = (const float*)d_in[0];
    const float* mu      = (const float*)d_in[1];
    const float* sigma   = (const float*)d_in[2];
    const float* label   = (const float*)d_in[3];
    const float* mask    = (const float*)d_in[4];
    const float* prob    = (const float*)d_in[5];
    float* out = (float*)d_out;

    k_main<<<NBLK, 256>>>(weights, mu, sigma, label, mask, prob, out);
    k_slog<<<dim3(8, 256), 256>>>(out);
}

// round 15
// speedup vs baseline: 1.3189x; 1.3189x over previous
#include <cuda_runtime.h>
#include <cuda_fp16.h>

#define NPIXT 262144   // B*H*W = 4*256*256
#define HWSZ  65536    // H*W
#define NCH   32
#define NBLK  1024     // NPIXT / 256
#define NSCAN 16
#define NTOT  (NBLK + NSCAN)
#define TINYF 1.17549435e-38f
#define INFF  __int_as_float(0x7f800000)

// ---------------- scratch (__device__ globals: allocation-free, zero-init) -----------
__device__ __half2 g_pk[NPIXT * 32];   // per-pixel, per-channel (mw, den) fp16 pairs
__device__ int   g_tblV[8 * NPIXT];    // rank table, valid
__device__ int   g_tblH[8 * NPIXT];    // rank table, hard
__device__ unsigned char g_cls[NPIXT]; // s | valid<<3 | hard<<4
__device__ unsigned g_bcnt[16 * NBLK]; // per-block counts + 1 (0 = pending); re-zeroed by k_scatter
__device__ int   g_boff[16 * NBLK];    // exclusive prefix
__device__ int   g_ticket;             // virtual block-id ticket (reset by finalize)
__device__ int   g_done;               // blocks-finished counter (reset by finalize)
__device__ int   g_count[8];
__device__ int   g_hcount[8];
__device__ float g_protoAcc[768];      // [k][s][c]; zero at entry of every launch
__device__ float g_posMW[8 * NCH];     // proto_mu_n * proto_w
__device__ float g_posDen[8 * NCH];    // proto_sigma * proto_w
__device__ float g_simL[8 * 7];        // sim/TEMP logits per (i,k)
__device__ float g_vnInv;

__device__ __forceinline__ unsigned ldvu(const unsigned* p) {
    return *(const volatile unsigned*)p;
}

// ---------------- threefry2x32 (JAX-compatible, partitionable mode) ----------------
__device__ __forceinline__ void tf2x32(unsigned k0, unsigned k1,
                                       unsigned x0, unsigned x1,
                                       unsigned& o0, unsigned& o1) {
    unsigned ks2 = k0 ^ k1 ^ 0x1BD11BDAu;
    x0 += k0; x1 += k1;
#define TF_R(r) { x0 += x1; x1 = __funnelshift_l(x1, x1, (r)); x1 ^= x0; }
    TF_R(13) TF_R(15) TF_R(26) TF_R(6)   x0 += k1;  x1 += ks2 + 1u;
    TF_R(17) TF_R(29) TF_R(16) TF_R(24)  x0 += ks2; x1 += k0  + 2u;
    TF_R(13) TF_R(15) TF_R(26) TF_R(6)   x0 += k0;  x1 += k1  + 3u;
    TF_R(17) TF_R(29) TF_R(16) TF_R(24)  x0 += k1;  x1 += ks2 + 4u;
    TF_R(13) TF_R(15) TF_R(26) TF_R(6)   x0 += ks2; x1 += k0  + 5u;
#undef TF_R
    o0 = x0; o1 = x1;
}

__device__ __forceinline__ unsigned rbits(unsigned k0, unsigned k1, unsigned idx) {
    unsigned a, b;
    tf2x32(k0, k1, 0u, idx, a, b);
    return a ^ b;
}
__device__ __forceinline__ float u01(unsigned bits) {
    return __uint_as_float((bits >> 9) | 0x3F800000u) - 1.0f;
}

// ============ kernel 1: classify + transpose (+16 scanner blocks) + finalize =========
__global__ void __launch_bounds__(256) k_main(const float* __restrict__ w_in,
                                              const float* __restrict__ mu_in,
                                              const float* __restrict__ sg_in,
                                              const float* __restrict__ label,
                                              const float* __restrict__ mask,
                                              const float* __restrict__ prob,
                                              float* out) {
    __shared__ float tw[32][33], tm[32][33], ts[32][33];
    __shared__ float acc[8][768];          // [warp][k*256 + s*32 + c]
    __shared__ unsigned char codes[256];
    __shared__ int wsum[8][8][2];          // [warp][class][flag]
    __shared__ int ws2[8];
    __shared__ int svblk;
    __shared__ int sdone;
    __shared__ float sMW[8][NCH], sDen[8][NCH];
    int t = threadIdx.x, warp = t >> 5, lane = t & 31;

    // virtual block id via scheduling-ordered ticket: scanners are last-scheduled
    if (t == 0) svblk = atomicAdd(&g_ticket, 1);
    __syncthreads();
    int blk = svblk;

    if (blk < NBLK) {
        // ================= publisher path: classify + transpose ======================
        for (int j = t; j < 8 * 768; j += 256) ((float*)acc)[j] = 0.f;

        int blockPix = blk * 256;
        int n = blockPix + t;
        int b = n >> 16, x = n & 65535;

        // ---- classify ----
        float mk = mask[b * HWSZ + x];
        int s = 0;
#pragma unroll
        for (int k = 0; k < 8; k++) {
            float lv = label[(b * 8 + k) * HWSZ + x];
            if (lv > 0.5f) s = k;
        }
        bool valid = mk > 0.0f;
        float pv = prob[(b * 8 + s) * HWSZ + x];
        bool hard = valid && (pv < 0.97f);
        codes[t] = (unsigned char)(s | (valid ? 8 : 0) | (hard ? 16 : 0));
        g_cls[n] = codes[t];

        unsigned lmlt2 = (1u << lane) - 1u;
        (void)lmlt2;
#pragma unroll
        for (int k = 0; k < 8; k++) {
            unsigned mv = __ballot_sync(0xffffffffu, valid && (s == k));
            unsigned mh = __ballot_sync(0xffffffffu, hard && (s == k));
            if (lane == 0) { wsum[warp][k][0] = __popc(mv); wsum[warp][k][1] = __popc(mh); }
        }
        __syncthreads();   // wsum, codes, acc-zero ready

        // ---- publish block counts early (value+1) ----
        if (t < 16) {
            int c16 = 0;
#pragma unroll
            for (int w2 = 0; w2 < 8; w2++) c16 += wsum[w2][t >> 1][t & 1];
            *(volatile unsigned*)&g_bcnt[t * NBLK + blk] = (unsigned)c16 + 1u;
        }

        // ---- staged transpose + prototype sums ----
        size_t base = (size_t)b * (NCH * HWSZ) + (blockPix & 65535);
#pragma unroll 1
        for (int st = 0; st < 8; st++) {
            int pixOfs = st * 32;
            __syncthreads();
#pragma unroll
            for (int i = 0; i < 4; i++) {
                int c = warp + i * 8;
                size_t a = base + (size_t)c * HWSZ + pixOfs + lane;
                tw[lane][c] = w_in[a];
                tm[lane][c] = mu_in[a];
                ts[lane][c] = sg_in[a];
            }
            __syncthreads();
#pragma unroll
            for (int j = 0; j < 4; j++) {
                int p = warp * 4 + j;
                int pin = pixOfs + p;
                int np = blockPix + pin;
                float wv = tw[p][lane];
                float mv = tm[p][lane];
                float sv = ts[p][lane];
                float nr2 = mv * mv;
#pragma unroll
                for (int ofs = 16; ofs; ofs >>= 1) nr2 += __shfl_xor_sync(0xffffffffu, nr2, ofs);
                float inv = 1.0f / fmaxf(sqrtf(nr2), 1e-12f);
                g_pk[(size_t)np * 32 + lane] = __floats2half2_rn((mv * inv) * wv, sv * wv);
                int pc = codes[pin];
                if (pc & 8) {
                    int ps = pc & 7;
                    float isw = __fdividef(wv, sv);
                    acc[warp][0 * 256 + ps * 32 + lane] += isw;
                    acc[warp][1 * 256 + ps * 32 + lane] += isw * mv;
                    acc[warp][2 * 256 + ps * 32 + lane] += __frcp_rn(wv);
                }
            }
        }
        __syncthreads();
#pragma unroll
        for (int j = 0; j < 3; j++) {
            int idx = t + j * 256;
            float sum = 0.f;
#pragma unroll
            for (int w2 = 0; w2 < 8; w2++) sum += acc[w2][idx];
            if (sum != 0.f) atomicAdd(&g_protoAcc[idx], sum);
        }
    } else {
        // ================= scanner path: one sequence per block ======================
        int seq = blk - NBLK;
        const unsigned* bp = g_bcnt + seq * NBLK;
        int bi4 = t * 4;
        unsigned v0, v1, v2, v3;
        while ((v0 = ldvu(bp + bi4 + 0)) == 0u) { }
        while ((v1 = ldvu(bp + bi4 + 1)) == 0u) { }
        while ((v2 = ldvu(bp + bi4 + 2)) == 0u) { }
        while ((v3 = ldvu(bp + bi4 + 3)) == 0u) { }
        v0--; v1--; v2--; v3--;
        int mysum = (int)(v0 + v1 + v2 + v3);
        // inclusive scan of per-thread sums
        int xv = mysum;
#pragma unroll
        for (int d = 1; d < 32; d <<= 1) {
            int y = __shfl_up_sync(0xffffffffu, xv, d);
            if (lane >= d) xv += y;
        }
        if (lane == 31) ws2[warp] = xv;
        __syncthreads();
        if (warp == 0) {
            int y = (lane < 8) ? ws2[lane] : 0;
#pragma unroll
            for (int d = 1; d < 8; d <<= 1) {
                int z = __shfl_up_sync(0xffffffffu, y, d);
                if (lane >= d) y += z;
            }
            if (lane < 8) ws2[lane] = y;
        }
        __syncthreads();
        int excl = xv - mysum + (warp ? ws2[warp - 1] : 0);
        int* op = g_boff + seq * NBLK + bi4;
        op[0] = excl; excl += (int)v0;
        op[1] = excl; excl += (int)v1;
        op[2] = excl; excl += (int)v2;
        op[3] = excl; excl += (int)v3;
        if (t == 255) {
            if (seq & 1) g_hcount[seq >> 1] = excl;
            else         g_count[seq >> 1]  = excl;
        }
    }

    // ---- last-done block runs finalize ----
    __threadfence();
    __syncthreads();
    if (t == 0) sdone = (atomicAdd(&g_done, 1) == NTOT - 1) ? 1 : 0;
    __syncthreads();
    if (sdone) {
        __threadfence();
        int ss = t >> 5, c = t & 31;
        float a0 = *(volatile float*)&g_protoAcc[0 * 256 + t];
        float a1 = *(volatile float*)&g_protoAcc[1 * 256 + t];
        float a2 = *(volatile float*)&g_protoAcc[2 * 256 + t];
        g_protoAcc[0 * 256 + t] = 0.f;     // restore invariants for next replay
        g_protoAcc[1 * 256 + t] = 0.f;
        g_protoAcc[2 * 256 + t] = 0.f;
        float psig = 1.0f / a0;
        float pmu = a1 / a0;
        float pw = 1.0f / a2;
        float nr2 = pmu * pmu;
#pragma unroll
        for (int ofs = 16; ofs; ofs >>= 1) nr2 += __shfl_xor_sync(0xffffffffu, nr2, ofs);
        float inv = 1.0f / fmaxf(sqrtf(nr2), 1e-12f);
        float mun = pmu * inv;
        float mw = mun * pw, den = psig * pw;
        g_posMW[ss * NCH + c] = mw;
        g_posDen[ss * NCH + c] = den;
        sMW[ss][c] = mw;
        sDen[ss][c] = den;
        __syncthreads();
        if (t < 56) {
            int i = t / 7, k = t % 7, o = (i + 1 + k) & 7;
            float sum = 0.f;
            for (int cc = 0; cc < NCH; cc++) {
                float d = sMW[i][cc] - sMW[o][cc];
                float dn = sDen[i][cc] + sDen[o][cc];
                sum += d * d / dn + logf(dn);
            }
            int co = *(volatile int*)&g_count[o];
            g_simL[i * 7 + k] = (co > 0) ? (-sum * (1.0f / 32.0f)) : -INFF;
        }
        if (t == 0) {
            int vn = 0;
            for (int s2 = 0; s2 < 8; s2++) vn += (*(volatile int*)&g_count[s2] > 0) ? 1 : 0;
            g_vnInv = (vn > 0) ? 1.0f / (float)vn : 0.f;
            out[0] = 0.f;
            g_done = 0;                    // reset for next replay
            g_ticket = 0;
        }
    }
}

// ============ kernel 2: scatter rank tables (+re-zero g_bcnt) ========================
__global__ void k_scatter() {
    int blk = blockIdx.x;
    int n = blk * 256 + threadIdx.x;
    int code = g_cls[n];
    int s = code & 7;
    bool valid = (code & 8) != 0, hard = (code & 16) != 0;
    __shared__ int wsum[8][8][2];  // [warp][class][flag]
    int warp = threadIdx.x >> 5, lane = threadIdx.x & 31;
    unsigned lmlt = (1u << lane) - 1u;
    int prefv = 0, prefh = 0;
#pragma unroll
    for (int k = 0; k < 8; k++) {
        unsigned mv = __ballot_sync(0xffffffffu, valid && (s == k));
        unsigned mh = __ballot_sync(0xffffffffu, hard && (s == k));
        if (s == k) { prefv = __popc(mv & lmlt); prefh = __popc(mh & lmlt); }
        if (lane == 0) { wsum[warp][k][0] = __popc(mv); wsum[warp][k][1] = __popc(mh); }
    }
    if (threadIdx.x < 16) g_bcnt[threadIdx.x * NBLK + blk] = 0u;  // replay invariant
    __syncthreads();
    int bofv = 0, bofh = 0;
    for (int w2 = 0; w2 < warp; w2++) { bofv += wsum[w2][s][0]; bofh += wsum[w2][s][1]; }
    if (valid) {
        int r = g_boff[(s * 2 + 0) * NBLK + blk] + bofv + prefv;
        g_tblV[s * NPIXT + r] = n;
        if (hard) {
            int rh = g_boff[(s * 2 + 1) * NBLK + blk] + bofh + prefh;
            g_tblH[s * NPIXT + rh] = n;
        }
    }
}

// ---------------- MLS logits ---------------------------------------------------------
__device__ __forceinline__ float mls_logit_h(const float* __restrict__ aMW,
                                             const float* __restrict__ aDen,
                                             const __half2* __restrict__ bpk) {
    const uint4* u = (const uint4*)bpk;   // 8 uint4, each = 4 channels of (mw,den)
    float total = 0.f;
#pragma unroll
    for (int g = 0; g < 8; g++) {
        uint4 v = u[g];
        const __half2* h = (const __half2*)&v;
        float qs = 0.f, prod = 1.f;
#pragma unroll
        for (int i = 0; i < 4; i++) {
            float2 md = __half22float2(h[i]);   // x=mw, y=den
            int c = g * 4 + i;
            float den = aDen[c] + md.y;
            float d = aMW[c] - md.x;
            qs += __fdividef(d * d, den);
            prod *= den;
        }
        total += qs + __logf(prod);
    }
    return -total * (1.0f / 32.0f);  // _mls/TEMP
}

__device__ __forceinline__ float mls_logit_f(const float* __restrict__ aMW,
                                             const float* __restrict__ aDen,
                                             const float* __restrict__ bMW,
                                             const float* __restrict__ bDen) {
    float total = 0.f;
#pragma unroll
    for (int g = 0; g < 4; g++) {
        float qs = 0.f, prod = 1.f;
#pragma unroll
        for (int i = 0; i < 8; i++) {
            int c = g * 8 + i;
            float den = aDen[c] + bDen[c];
            float d = aMW[c] - bMW[c];
            qs += __fdividef(d * d, den);
            prod *= den;
        }
        total += qs + __logf(prod);
    }
    return -total * (1.0f / 32.0f);
}

// ============ kernel 3: fused sampling + logits + logsumexp + CE =====================
__global__ void __launch_bounds__(256) k_slog(float* out) {
    int i = blockIdx.x, q = blockIdx.y, t = threadIdx.x;
    int warp = t >> 5, lane = t & 31;
    __shared__ unsigned sk[4];           // k2a,k2b,k3a,k3b
    __shared__ int sap;
    __shared__ float sexp[7];            // exp(-sim/TEMP) for exponential-race argmin
    __shared__ float aMW[NCH], aDen[NCH];
    __shared__ float sred[8];

    if (t < 7) sexp[t] = __expf(-g_simL[i * 7 + t]);
    // parallel prologue: three warps derive the three key chains
    if (t == 0) {
        unsigned ka, kb, k1a, k1b;
        tf2x32(0u, 42u, 0u, (unsigned)i, ka, kb);   // keys[i]
        tf2x32(ka, kb, 0u, 0u, k1a, k1b);           // k1
        float u = u01(rbits(k1a, k1b, (unsigned)q));
        int hc = g_hcount[i];
        int r = (int)(u * (float)hc);
        int cl = hc - 1; if (cl < 0) cl = 0;
        if (r > cl) r = cl;
        if (r < 0) r = 0;
        int ap = (hc > 0) ? g_tblH[i * NPIXT + r] : 0;
        if (ap < 0) ap = 0;
        if (ap >= NPIXT) ap = NPIXT - 1;
        sap = ap;
    } else if (t == 32) {
        unsigned ka, kb, a, b2;
        tf2x32(0u, 42u, 0u, (unsigned)i, ka, kb);
        tf2x32(ka, kb, 0u, 1u, a, b2);              // k2
        sk[0] = a; sk[1] = b2;
    } else if (t == 64) {
        unsigned ka, kb, a, b2;
        tf2x32(0u, 42u, 0u, (unsigned)i, ka, kb);
        tf2x32(ka, kb, 0u, 2u, a, b2);              // k3
        sk[2] = a; sk[3] = b2;
    }
    __syncthreads();
    if (t < NCH) {
        float2 md = __half22float2(g_pk[(size_t)sap * 32 + t]);
        aMW[t] = md.x;
        aDen[t] = md.y;
    }
    unsigned k2a = sk[0], k2b = sk[1], k3a = sk[2], k3b = sk[3];

    // ---- negative class sampling via exponential race (argmin (-ln u)*exp(-sim)) ----
    unsigned j = (unsigned)(q * 256 + t);
    unsigned b7 = j * 7u;
    float wmin = INFF;
    int bi = 0;
#pragma unroll
    for (int k = 0; k < 7; k++) {
        float u = u01(rbits(k2a, k2b, b7 + k));
        u = fmaxf(u + TINYF, TINYF);
        float wv = -__logf(u) * sexp[k];
        if (wv < wmin) { wmin = wv; bi = k; }
    }
    int cls = (i + 1 + bi) & 7;
    int cnt = g_count[cls];
    float u3 = u01(rbits(k3a, k3b, j));
    int r = (int)(u3 * (float)cnt);
    int cl = cnt - 1; if (cl < 0) cl = 0;
    if (r > cl) r = cl;
    if (r < 0) r = 0;
    int p = g_tblV[cls * NPIXT + r];
    if (p < 0) p = 0;
    if (p >= NPIXT) p = NPIXT - 1;
    __syncthreads();   // anchor smem ready

    // ---- logits: lg0 = this thread's NEGATIVE, lg1 (t==0 only) = POSITIVE ----
    float lg0 = mls_logit_h(aMW, aDen, g_pk + (size_t)p * 32);
    float lg1 = (t == 0) ? mls_logit_f(aMW, aDen, g_posMW + i * NCH, g_posDen + i * NCH)
                         : 0.f;

    // ---- logsumexp with fixed shift M=0 (logits bounded above ~4) ----
    float ex = __expf(lg0) + ((t == 0) ? __expf(lg1) : 0.f);
#pragma unroll
    for (int ofs = 16; ofs; ofs >>= 1) ex += __shfl_xor_sync(0xffffffffu, ex, ofs);
    if (lane == 0) sred[warp] = ex;
    __syncthreads();
    if (t == 0) {
        float sum = 0.f;
#pragma unroll
        for (int w2 = 0; w2 < 8; w2++) sum += sred[w2];
        float lse = __logf(sum);
        bool ok = (g_hcount[i] > 0) && (g_count[i] > 0);
        if (ok) atomicAdd(out, (lse - lg1) * g_vnInv * (1.0f / 256.0f));
    }
}

// ---------------- launch ----------------
extern "C" void kernel_launch(void* const* d_in, const int* in_sizes, int n_in,
                              void* d_out, int out_size) {
    const float* weights = (const float*)d_in[0];
    const float* mu      = (const float*)d_in[1];
    const float* sigma   = (const float*)d_in[2];
    const float* label   = (const float*)d_in[3];
    const float* mask    = (const float*)d_in[4];
    const float* prob    = (const float*)d_in[5];
    float* out = (float*)d_out;

    k_main<<<NTOT, 256>>>(weights, mu, sigma, label, mask, prob, out);
    k_scatter<<<NBLK, 256>>>();
    k_slog<<<dim3(8, 256), 256>>>(out);
}

// round 16
// speedup vs baseline: 1.4061x; 1.0661x over previous
#include <cuda_runtime.h>
#include <cuda_fp16.h>

#define NPIXT 262144   // B*H*W = 4*256*256
#define HWSZ  65536    // H*W
#define NCH   32
#define NBLK  1024     // NPIXT / 256
#define NSCAN 16
#define NTOT  (NBLK + NSCAN)
#define TINYF 1.17549435e-38f
#define INFF  __int_as_float(0x7f800000)

// ---------------- scratch (__device__ globals: allocation-free, zero-init) -----------
__device__ __half2 g_pk[NPIXT * 32];   // per-pixel, per-channel (mw, den) fp16 pairs
__device__ int   g_tblV[8 * NPIXT];    // rank table, valid
__device__ int   g_tblH[8 * NPIXT];    // rank table, hard
__device__ int   g_info[NPIXT];        // s | valid<<3 | hard<<4 | rankV<<8 | rankH<<16
__device__ unsigned g_bcnt[16 * NBLK]; // per-block counts + 1 (0 = pending); re-zeroed by k_scatter
__device__ int   g_boff[16 * NBLK];    // exclusive prefix
__device__ int   g_ticket;             // virtual block-id ticket (reset by finalize)
__device__ int   g_done;               // blocks-finished counter (reset by finalize)
__device__ int   g_count[8];
__device__ int   g_hcount[8];
__device__ float g_protoAcc[768];      // [k][s][c]; zero at entry of every launch
__device__ float g_posMW[8 * NCH];     // proto_mu_n * proto_w
__device__ float g_posDen[8 * NCH];    // proto_sigma * proto_w
__device__ float g_simL[8 * 7];        // sim/TEMP logits per (i,k)
__device__ float g_vnInv;

__device__ __forceinline__ unsigned ldvu(const unsigned* p) {
    return *(const volatile unsigned*)p;
}

// ---------------- threefry2x32 (JAX-compatible, partitionable mode) ----------------
__device__ __forceinline__ void tf2x32(unsigned k0, unsigned k1,
                                       unsigned x0, unsigned x1,
                                       unsigned& o0, unsigned& o1) {
    unsigned ks2 = k0 ^ k1 ^ 0x1BD11BDAu;
    x0 += k0; x1 += k1;
#define TF_R(r) { x0 += x1; x1 = __funnelshift_l(x1, x1, (r)); x1 ^= x0; }
    TF_R(13) TF_R(15) TF_R(26) TF_R(6)   x0 += k1;  x1 += ks2 + 1u;
    TF_R(17) TF_R(29) TF_R(16) TF_R(24)  x0 += ks2; x1 += k0  + 2u;
    TF_R(13) TF_R(15) TF_R(26) TF_R(6)   x0 += k0;  x1 += k1  + 3u;
    TF_R(17) TF_R(29) TF_R(16) TF_R(24)  x0 += k1;  x1 += ks2 + 4u;
    TF_R(13) TF_R(15) TF_R(26) TF_R(6)   x0 += ks2; x1 += k0  + 5u;
#undef TF_R
    o0 = x0; o1 = x1;
}

__device__ __forceinline__ unsigned rbits(unsigned k0, unsigned k1, unsigned idx) {
    unsigned a, b;
    tf2x32(k0, k1, 0u, idx, a, b);
    return a ^ b;
}
__device__ __forceinline__ float u01(unsigned bits) {
    return __uint_as_float((bits >> 9) | 0x3F800000u) - 1.0f;
}

// ============ kernel 1: classify + transpose (+16 scanner blocks) + finalize =========
__global__ void __launch_bounds__(256) k_main(const float* __restrict__ w_in,
                                              const float* __restrict__ mu_in,
                                              const float* __restrict__ sg_in,
                                              const float* __restrict__ label,
                                              const float* __restrict__ mask,
                                              const float* __restrict__ prob,
                                              float* out) {
    __shared__ float tw[32][33], tm[32][33], ts[32][33];
    __shared__ float acc[8][768];          // [warp][k*256 + s*32 + c]
    __shared__ unsigned char codes[256];
    __shared__ int wsum[8][8][2];          // [warp][class][flag]
    __shared__ int ws2[8];
    __shared__ int svblk;
    __shared__ int sdone;
    __shared__ float sMW[8][NCH], sDen[8][NCH];
    int t = threadIdx.x, warp = t >> 5, lane = t & 31;

    // virtual block id via scheduling-ordered ticket: scanners are last-scheduled
    if (t == 0) svblk = atomicAdd(&g_ticket, 1);
    __syncthreads();
    int blk = svblk;

    if (blk < NBLK) {
        // ================= publisher path: classify + transpose ======================
        for (int j = t; j < 8 * 768; j += 256) ((float*)acc)[j] = 0.f;

        int blockPix = blk * 256;
        int n = blockPix + t;
        int b = n >> 16, x = n & 65535;

        // ---- classify ----
        float mk = mask[b * HWSZ + x];
        int s = 0;
#pragma unroll
        for (int k = 0; k < 8; k++) {
            float lv = label[(b * 8 + k) * HWSZ + x];
            if (lv > 0.5f) s = k;
        }
        bool valid = mk > 0.0f;
        float pv = prob[(b * 8 + s) * HWSZ + x];
        bool hard = valid && (pv < 0.97f);
        codes[t] = (unsigned char)(s | (valid ? 8 : 0) | (hard ? 16 : 0));

        unsigned lmlt = (1u << lane) - 1u;
        int prefv = 0, prefh = 0;
#pragma unroll
        for (int k = 0; k < 8; k++) {
            unsigned mv = __ballot_sync(0xffffffffu, valid && (s == k));
            unsigned mh = __ballot_sync(0xffffffffu, hard && (s == k));
            if (s == k) { prefv = __popc(mv & lmlt); prefh = __popc(mh & lmlt); }
            if (lane == 0) { wsum[warp][k][0] = __popc(mv); wsum[warp][k][1] = __popc(mh); }
        }
        __syncthreads();   // wsum, codes, acc-zero ready

        // ---- publish block counts early (value+1) ----
        if (t < 16) {
            int c16 = 0;
#pragma unroll
            for (int w2 = 0; w2 < 8; w2++) c16 += wsum[w2][t >> 1][t & 1];
            *(volatile unsigned*)&g_bcnt[t * NBLK + blk] = (unsigned)c16 + 1u;
        }

        // ---- in-block ranks -> packed info word ----
        {
            int bofv = 0, bofh = 0;
            for (int w2 = 0; w2 < warp; w2++) { bofv += wsum[w2][s][0]; bofh += wsum[w2][s][1]; }
            int rv = bofv + prefv, rh = bofh + prefh;
            g_info[n] = (int)codes[t] | (rv << 8) | (rh << 16);
        }

        // ---- staged transpose, software-pipelined with register prefetch ----
        size_t base = (size_t)b * (NCH * HWSZ) + (blockPix & 65535);
        float rw[4], rm[4], rs[4];
#pragma unroll
        for (int i = 0; i < 4; i++) {          // prefetch stage 0
            int c = warp + i * 8;
            size_t a = base + (size_t)c * HWSZ + lane;
            rw[i] = w_in[a]; rm[i] = mu_in[a]; rs[i] = sg_in[a];
        }
#pragma unroll 1
        for (int st = 0; st < 8; st++) {
            __syncthreads();                   // tiles free (phase2 of st-1 done)
#pragma unroll
            for (int i = 0; i < 4; i++) {
                int c = warp + i * 8;
                tw[lane][c] = rw[i];
                tm[lane][c] = rm[i];
                ts[lane][c] = rs[i];
            }
            __syncthreads();                   // tiles ready
            if (st < 7) {                      // issue next stage's loads now;
#pragma unroll                                 // they overlap phase-2 compute below
                for (int i = 0; i < 4; i++) {
                    int c = warp + i * 8;
                    size_t a = base + (size_t)c * HWSZ + (st + 1) * 32 + lane;
                    rw[i] = w_in[a]; rm[i] = mu_in[a]; rs[i] = sg_in[a];
                }
            }
            int pixOfs = st * 32;
#pragma unroll
            for (int j = 0; j < 4; j++) {
                int p = warp * 4 + j;
                int pin = pixOfs + p;
                int np = blockPix + pin;
                float wv = tw[p][lane];
                float mv = tm[p][lane];
                float sv = ts[p][lane];
                float nr2 = mv * mv;
#pragma unroll
                for (int ofs = 16; ofs; ofs >>= 1) nr2 += __shfl_xor_sync(0xffffffffu, nr2, ofs);
                float inv = 1.0f / fmaxf(sqrtf(nr2), 1e-12f);
                g_pk[(size_t)np * 32 + lane] = __floats2half2_rn((mv * inv) * wv, sv * wv);
                int pc = codes[pin];
                if (pc & 8) {
                    int ps = pc & 7;
                    float isw = __fdividef(wv, sv);
                    acc[warp][0 * 256 + ps * 32 + lane] += isw;
                    acc[warp][1 * 256 + ps * 32 + lane] += isw * mv;
                    acc[warp][2 * 256 + ps * 32 + lane] += __frcp_rn(wv);
                }
            }
        }
        __syncthreads();
#pragma unroll
        for (int j = 0; j < 3; j++) {
            int idx = t + j * 256;
            float sum = 0.f;
#pragma unroll
            for (int w2 = 0; w2 < 8; w2++) sum += acc[w2][idx];
            if (sum != 0.f) atomicAdd(&g_protoAcc[idx], sum);
        }
    } else {
        // ================= scanner path: one sequence per block ======================
        int seq = blk - NBLK;
        const unsigned* bp = g_bcnt + seq * NBLK;
        int bi4 = t * 4;
        unsigned v0, v1, v2, v3;
        while ((v0 = ldvu(bp + bi4 + 0)) == 0u) { }
        while ((v1 = ldvu(bp + bi4 + 1)) == 0u) { }
        while ((v2 = ldvu(bp + bi4 + 2)) == 0u) { }
        while ((v3 = ldvu(bp + bi4 + 3)) == 0u) { }
        v0--; v1--; v2--; v3--;
        int mysum = (int)(v0 + v1 + v2 + v3);
        int xv = mysum;
#pragma unroll
        for (int d = 1; d < 32; d <<= 1) {
            int y = __shfl_up_sync(0xffffffffu, xv, d);
            if (lane >= d) xv += y;
        }
        if (lane == 31) ws2[warp] = xv;
        __syncthreads();
        if (warp == 0) {
            int y = (lane < 8) ? ws2[lane] : 0;
#pragma unroll
            for (int d = 1; d < 8; d <<= 1) {
                int z = __shfl_up_sync(0xffffffffu, y, d);
                if (lane >= d) y += z;
            }
            if (lane < 8) ws2[lane] = y;
        }
        __syncthreads();
        int excl = xv - mysum + (warp ? ws2[warp - 1] : 0);
        int* op = g_boff + seq * NBLK + bi4;
        op[0] = excl; excl += (int)v0;
        op[1] = excl; excl += (int)v1;
        op[2] = excl; excl += (int)v2;
        op[3] = excl; excl += (int)v3;
        if (t == 255) {
            if (seq & 1) g_hcount[seq >> 1] = excl;
            else         g_count[seq >> 1]  = excl;
        }
    }

    // ---- last-done block runs finalize ----
    __threadfence();
    __syncthreads();
    if (t == 0) sdone = (atomicAdd(&g_done, 1) == NTOT - 1) ? 1 : 0;
    __syncthreads();
    if (sdone) {
        __threadfence();
        int ss = t >> 5, c = t & 31;
        float a0 = *(volatile float*)&g_protoAcc[0 * 256 + t];
        float a1 = *(volatile float*)&g_protoAcc[1 * 256 + t];
        float a2 = *(volatile float*)&g_protoAcc[2 * 256 + t];
        g_protoAcc[0 * 256 + t] = 0.f;     // restore invariants for next replay
        g_protoAcc[1 * 256 + t] = 0.f;
        g_protoAcc[2 * 256 + t] = 0.f;
        float psig = 1.0f / a0;
        float pmu = a1 / a0;
        float pw = 1.0f / a2;
        float nr2 = pmu * pmu;
#pragma unroll
        for (int ofs = 16; ofs; ofs >>= 1) nr2 += __shfl_xor_sync(0xffffffffu, nr2, ofs);
        float inv = 1.0f / fmaxf(sqrtf(nr2), 1e-12f);
        float mun = pmu * inv;
        float mw = mun * pw, den = psig * pw;
        g_posMW[ss * NCH + c] = mw;
        g_posDen[ss * NCH + c] = den;
        sMW[ss][c] = mw;
        sDen[ss][c] = den;
        __syncthreads();
        if (t < 56) {
            int i = t / 7, k = t % 7, o = (i + 1 + k) & 7;
            float sum = 0.f;
            for (int cc = 0; cc < NCH; cc++) {
                float d = sMW[i][cc] - sMW[o][cc];
                float dn = sDen[i][cc] + sDen[o][cc];
                sum += d * d / dn + logf(dn);
            }
            int co = *(volatile int*)&g_count[o];
            g_simL[i * 7 + k] = (co > 0) ? (-sum * (1.0f / 32.0f)) : -INFF;
        }
        if (t == 0) {
            int vn = 0;
            for (int s2 = 0; s2 < 8; s2++) vn += (*(volatile int*)&g_count[s2] > 0) ? 1 : 0;
            g_vnInv = (vn > 0) ? 1.0f / (float)vn : 0.f;
            out[0] = 0.f;
            g_done = 0;                    // reset for next replay
            g_ticket = 0;
        }
    }
}

// ============ kernel 2: scatter rank tables from packed info (+re-zero g_bcnt) =======
__global__ void k_scatter() {
    __shared__ int sboff[16];
    int blk = blockIdx.x;
    int t = threadIdx.x;
    int n = blk * 256 + t;
    if (t < 16) {
        sboff[t] = g_boff[t * NBLK + blk];
        g_bcnt[t * NBLK + blk] = 0u;       // replay invariant
    }
    int info = g_info[n];
    __syncthreads();
    if (info & 8) {
        int s = info & 7;
        int r = sboff[s * 2 + 0] + ((info >> 8) & 255);
        g_tblV[s * NPIXT + r] = n;
        if (info & 16) {
            int rh = sboff[s * 2 + 1] + ((info >> 16) & 255);
            g_tblH[s * NPIXT + rh] = n;
        }
    }
}

// ---------------- MLS logits ---------------------------------------------------------
__device__ __forceinline__ float mls_logit_h(const float* __restrict__ aMW,
                                             const float* __restrict__ aDen,
                                             const __half2* __restrict__ bpk) {
    const uint4* u = (const uint4*)bpk;   // 8 uint4, each = 4 channels of (mw,den)
    float total = 0.f;
#pragma unroll
    for (int g = 0; g < 8; g++) {
        uint4 v = u[g];
        const __half2* h = (const __half2*)&v;
        float qs = 0.f, prod = 1.f;
#pragma unroll
        for (int i = 0; i < 4; i++) {
            float2 md = __half22float2(h[i]);   // x=mw, y=den
            int c = g * 4 + i;
            float den = aDen[c] + md.y;
            float d = aMW[c] - md.x;
            qs += __fdividef(d * d, den);
            prod *= den;
        }
        total += qs + __logf(prod);
    }
    return -total * (1.0f / 32.0f);  // _mls/TEMP
}

__device__ __forceinline__ float mls_logit_f(const float* __restrict__ aMW,
                                             const float* __restrict__ aDen,
                                             const float* __restrict__ bMW,
                                             const float* __restrict__ bDen) {
    float total = 0.f;
#pragma unroll
    for (int g = 0; g < 4; g++) {
        float qs = 0.f, prod = 1.f;
#pragma unroll
        for (int i = 0; i < 8; i++) {
            int c = g * 8 + i;
            float den = aDen[c] + bDen[c];
            float d = aMW[c] - bMW[c];
            qs += __fdividef(d * d, den);
            prod *= den;
        }
        total += qs + __logf(prod);
    }
    return -total * (1.0f / 32.0f);
}

// ============ kernel 3: fused sampling + logits + logsumexp + CE =====================
__global__ void __launch_bounds__(256) k_slog(float* out) {
    int i = blockIdx.x, q = blockIdx.y, t = threadIdx.x;
    int warp = t >> 5, lane = t & 31;
    __shared__ unsigned sk[4];           // k2a,k2b,k3a,k3b
    __shared__ int sap;
    __shared__ float sexp[7];            // exp(-sim/TEMP) for exponential-race argmin
    __shared__ float aMW[NCH], aDen[NCH];
    __shared__ float sred[8];

    if (t < 7) sexp[t] = __expf(-g_simL[i * 7 + t]);
    // parallel prologue: three warps derive the three key chains
    if (t == 0) {
        unsigned ka, kb, k1a, k1b;
        tf2x32(0u, 42u, 0u, (unsigned)i, ka, kb);   // keys[i]
        tf2x32(ka, kb, 0u, 0u, k1a, k1b);           // k1
        float u = u01(rbits(k1a, k1b, (unsigned)q));
        int hc = g_hcount[i];
        int r = (int)(u * (float)hc);
        int cl = hc - 1; if (cl < 0) cl = 0;
        if (r > cl) r = cl;
        if (r < 0) r = 0;
        int ap = (hc > 0) ? g_tblH[i * NPIXT + r] : 0;
        if (ap < 0) ap = 0;
        if (ap >= NPIXT) ap = NPIXT - 1;
        sap = ap;
    } else if (t == 32) {
        unsigned ka, kb, a, b2;
        tf2x32(0u, 42u, 0u, (unsigned)i, ka, kb);
        tf2x32(ka, kb, 0u, 1u, a, b2);              // k2
        sk[0] = a; sk[1] = b2;
    } else if (t == 64) {
        unsigned ka, kb, a, b2;
        tf2x32(0u, 42u, 0u, (unsigned)i, ka, kb);
        tf2x32(ka, kb, 0u, 2u, a, b2);              // k3
        sk[2] = a; sk[3] = b2;
    }
    __syncthreads();
    if (t < NCH) {
        float2 md = __half22float2(g_pk[(size_t)sap * 32 + t]);
        aMW[t] = md.x;
        aDen[t] = md.y;
    }
    unsigned k2a = sk[0], k2b = sk[1], k3a = sk[2], k3b = sk[3];

    // ---- negative class sampling via exponential race (argmin (-ln u)*exp(-sim)) ----
    unsigned j = (unsigned)(q * 256 + t);
    unsigned b7 = j * 7u;
    float wmin = INFF;
    int bi = 0;
#pragma unroll
    for (int k = 0; k < 7; k++) {
        float u = u01(rbits(k2a, k2b, b7 + k));
        u = fmaxf(u + TINYF, TINYF);
        float wv = -__logf(u) * sexp[k];
        if (wv < wmin) { wmin = wv; bi = k; }
    }
    int cls = (i + 1 + bi) & 7;
    int cnt = g_count[cls];
    float u3 = u01(rbits(k3a, k3b, j));
    int r = (int)(u3 * (float)cnt);
    int cl = cnt - 1; if (cl < 0) cl = 0;
    if (r > cl) r = cl;
    if (r < 0) r = 0;
    int p = g_tblV[cls * NPIXT + r];
    if (p < 0) p = 0;
    if (p >= NPIXT) p = NPIXT - 1;
    __syncthreads();   // anchor smem ready

    // ---- logits: lg0 = this thread's NEGATIVE, lg1 (t==0 only) = POSITIVE ----
    float lg0 = mls_logit_h(aMW, aDen, g_pk + (size_t)p * 32);
    float lg1 = (t == 0) ? mls_logit_f(aMW, aDen, g_posMW + i * NCH, g_posDen + i * NCH)
                         : 0.f;

    // ---- logsumexp with fixed shift M=0 (logits bounded above ~4) ----
    float ex = __expf(lg0) + ((t == 0) ? __expf(lg1) : 0.f);
#pragma unroll
    for (int ofs = 16; ofs; ofs >>= 1) ex += __shfl_xor_sync(0xffffffffu, ex, ofs);
    if (lane == 0) sred[warp] = ex;
    __syncthreads();
    if (t == 0) {
        float sum = 0.f;
#pragma unroll
        for (int w2 = 0; w2 < 8; w2++) sum += sred[w2];
        float lse = __logf(sum);
        bool ok = (g_hcount[i] > 0) && (g_count[i] > 0);
        if (ok) atomicAdd(out, (lse - lg1) * g_vnInv * (1.0f / 256.0f));
    }
}

// ---------------- launch ----------------
extern "C" void kernel_launch(void* const* d_in, const int* in_sizes, int n_in,
                              void* d_out, int out_size) {
    const float* weights = (const float*)d_in[0];
    const float* mu      = (const float*)d_in[1];
    const float* sigma   = (const float*)d_in[2];
    const float* label   = (const float*)d_in[3];
    const float* mask    = (const float*)d_in[4];
    const float* prob    = (const float*)d_in[5];
    float* out = (float*)d_out;

    k_main<<<NTOT, 256>>>(weights, mu, sigma, label, mask, prob, out);
    k_scatter<<<NBLK, 256>>>();
    k_slog<<<dim3(8, 256), 256>>>(out);
}